// round 5
// baseline (speedup 1.0000x reference)
#include <cuda_runtime.h>
#include <cuda_bf16.h>

// Problem constants
#define BB 64
#define LL 550
#define DD 768
#define RR 3
#define PP 50
#define LEN_KEEP (LL - RR * PP)   // 400
#define D4 (DD / 4)               // 192 float4 per feature row

#define NSORT 1024                // padded sort size (pow2 >= 550)
#define THREADS 512
#define CTAS_PER_B 4              // gather quarters per batch row
#define ROWS_PER_Q (LEN_KEEP / CTAS_PER_B)        // 100
#define F4_PER_Q (ROWS_PER_Q * D4)                // 19200

typedef unsigned long long u64;

// ---------------------------------------------------------------------------
// Fully fused kernel. grid = 256 (4 CTAs per batch row), block = 512.
// Each CTA: build keys -> bitonic sort (redundant across the 4 CTAs of a
// batch, but cheap) -> q==0 CTA writes mask/ids_restore -> all CTAs gather
// their quarter of the kept rows using shared-memory src indices.
// No global scratch, no inter-CTA sync, single launch.
// ---------------------------------------------------------------------------
__global__ __launch_bounds__(THREADS)
void fused_mask_kernel(const float4* __restrict__ x,
                       const float*  __restrict__ noise,
                       const int*    __restrict__ indexes,
                       float*        __restrict__ out,
                       float4*       __restrict__ out4)
{
    __shared__ u64 s_keys[NSORT];
    __shared__ int s_src[LEN_KEEP];   // float4-base of source row per rank

    const int tid = threadIdx.x;
    const int b   = blockIdx.x >> 2;       // batch row
    const int q   = blockIdx.x & 3;        // gather quarter

    const int i0 = indexes[b * RR + 0];
    const int i1 = indexes[b * RR + 1];
    const int i2 = indexes[b * RR + 2];

    // Build composite keys: upper 32 = float bits (all values non-negative ->
    // bit pattern order-isomorphic to value), lower 32 = index (stable ties).
    for (int j = tid; j < LL; j += THREADS) {
        const int blk = j / PP;
        float v = (blk == i0 || blk == i1 || blk == i2) ? 2.0f
                                                        : noise[b * LL + j];
        s_keys[j] = ((u64)__float_as_uint(v) << 32) | (unsigned)j;
    }
    for (int j = LL + tid; j < NSORT; j += THREADS)
        s_keys[j] = 0xFFFFFFFFFFFFFFFFULL;     // padding sorts to the end

    // Bitonic sort, ascending. 512 threads handle 512 pairs per stage.
    for (int k = 2; k <= NSORT; k <<= 1) {
        for (int j = k >> 1; j > 0; j >>= 1) {
            __syncthreads();
            const int low = tid & (j - 1);
            const int a1  = ((tid ^ low) << 1) | low;   // bit j inserted as 0
            const int a2  = a1 | j;
            const bool up = ((a1 & k) == 0);
            const u64 ka = s_keys[a1];
            const u64 kb = s_keys[a2];
            if ((ka > kb) == up) { s_keys[a1] = kb; s_keys[a2] = ka; }
        }
    }
    __syncthreads();

    // sorted[r] = original index with rank r  (== ids_shuffle[r])
    const int OFF_MASK = BB * LEN_KEEP * DD;   // 19,660,800
    const int OFF_IDS  = OFF_MASK + BB * LL;   // 19,696,000

    for (int r = tid; r < LL; r += THREADS) {
        const int idx = (int)(unsigned)s_keys[r];      // lower 32 bits
        if (q == 0) {
            out[OFF_IDS  + b * LL + idx] = (float)r;               // ids_restore
            out[OFF_MASK + b * LL + idx] = (r >= LEN_KEEP) ? 1.0f : 0.0f;
        }
        if (r < LEN_KEEP)
            s_src[r] = (b * LL + idx) * D4;
    }
    __syncthreads();

    // Gather this CTA's quarter: ranks [q*100, q*100+100), 19200 float4.
    const int out_base = (b * LEN_KEEP + q * ROWS_PER_Q) * D4;
    #pragma unroll 4
    for (int idx = tid; idx < F4_PER_Q; idx += THREADS) {
        const int row = idx / D4;                 // 0..99
        const int col = idx - row * D4;
        const float4 v = __ldcs(&x[s_src[q * ROWS_PER_Q + row] + col]);
        __stcs(&out4[out_base + idx], v);
    }
}

// ---------------------------------------------------------------------------
extern "C" void kernel_launch(void* const* d_in, const int* in_sizes, int n_in,
                              void* d_out, int out_size)
{
    const float* x       = (const float*)d_in[0];  // (64, 550, 768) f32
    const float* noise   = (const float*)d_in[1];  // (64, 550) f32
    const int*   indexes = (const int*)  d_in[2];  // (64, 3) i32
    float* out = (float*)d_out;   // [x_masked | mask | ids_restore] as f32

    fused_mask_kernel<<<BB * CTAS_PER_B, THREADS>>>(
        (const float4*)x, noise, indexes, out, (float4*)out);
}

// round 6
// speedup vs baseline: 1.1188x; 1.1188x over previous
#include <cuda_runtime.h>
#include <cuda_bf16.h>

// Problem constants
#define BB 64
#define LL 550
#define DD 768
#define RR 3
#define PP 50
#define LEN_KEEP (LL - RR * PP)   // 400
#define D4 (DD / 4)               // 192 float4 per feature row

#define THREADS 256
#define RANK_CTAS_PER_B 2
#define RANK_CTAS (BB * RANK_CTAS_PER_B)          // 128
#define HALF_LEN 275                              // positions per rank CTA

#define ROWS_PER_BLK 8
#define F4_PER_BLK (ROWS_PER_BLK * D4)            // 1536 = 6 * 256
#define GATHER_PER_B (LEN_KEEP / ROWS_PER_BLK)    // 50
#define GATHER_CTAS (BB * GATHER_PER_B)           // 3200

// Global scratch + handshake state. flag/done self-reset each launch, so the
// kernel is graph-replay safe and deterministic.
__device__ int g_keep[BB * LEN_KEEP];
__device__ volatile int g_flag[BB];
__device__ int g_done[BB];

__global__ __launch_bounds__(THREADS)
void fused_kernel(const float4* __restrict__ x,
                  const float*  __restrict__ noise,
                  const int*    __restrict__ indexes,
                  float*        __restrict__ out,
                  float4*       __restrict__ out4)
{
    __shared__ unsigned int sh_bits[LL];   // rank path
    __shared__ int s_src[ROWS_PER_BLK];    // gather path

    const int tid = threadIdx.x;
    const int bid = blockIdx.x;

    if (bid < RANK_CTAS) {
        // ----------------- producer: stable rank by counting ---------------
        const int b    = bid >> 1;
        const int half = bid & 1;

        const int i0 = indexes[b * RR + 0];
        const int i1 = indexes[b * RR + 1];
        const int i2 = indexes[b * RR + 2];

        for (int j = tid; j < LL; j += THREADS) {
            const int blk = j / PP;
            float v = (blk == i0 || blk == i1 || blk == i2) ? 2.0f
                                                            : noise[b * LL + j];
            sh_bits[j] = __float_as_uint(v);  // non-negative -> bits ~ value
        }
        __syncthreads();

        const int base = half * HALF_LEN;
        const int p0 = base + tid;                 // always < base+275
        const int p1 = p0 + THREADS;
        const bool has1 = (p1 < base + HALF_LEN) && (p1 < LL);
        const bool has0 = (p0 < LL);

        const unsigned my0 = has0 ? sh_bits[p0] : 0u;
        const unsigned my1 = has1 ? sh_bits[p1] : 0u;
        int r0 = 0, r1 = 0;
        #pragma unroll 10
        for (int j = 0; j < LL; j++) {
            const unsigned bj = sh_bits[j];        // warp-uniform broadcast
            r0 += (int)((bj < my0) || ((bj == my0) && (j < p0)));
            r1 += (int)((bj < my1) || ((bj == my1) && (j < p1)));
        }

        const int OFF_MASK = BB * LEN_KEEP * DD;
        const int OFF_IDS  = OFF_MASK + BB * LL;

        if (has0) {
            out[OFF_MASK + b * LL + p0] = (r0 >= LEN_KEEP) ? 1.0f : 0.0f;
            out[OFF_IDS  + b * LL + p0] = (float)r0;
            if (r0 < LEN_KEEP) g_keep[b * LEN_KEEP + r0] = p0;
        }
        if (has1) {
            out[OFF_MASK + b * LL + p1] = (r1 >= LEN_KEEP) ? 1.0f : 0.0f;
            out[OFF_IDS  + b * LL + p1] = (float)r1;
            if (r1 < LEN_KEEP) g_keep[b * LEN_KEEP + r1] = p1;
        }

        // Publish: make g_keep visible, then signal.
        __syncthreads();
        __threadfence();
        if (tid == 0) atomicAdd((int*)&g_flag[b], 1);
    } else {
        // ----------------- consumer: gather 8 kept rows --------------------
        const int g   = bid - RANK_CTAS;           // 0..3199
        const int b   = g / GATHER_PER_B;
        const int sub = g - b * GATHER_PER_B;      // 0..49

        if (tid == 0) {
            // Spin until both rank halves of batch b have published.
            while (g_flag[b] < RANK_CTAS_PER_B) __nanosleep(64);
            __threadfence();                       // acquire
        }
        __syncthreads();

        if (tid < ROWS_PER_BLK) {
            const int rowg = b * LEN_KEEP + sub * ROWS_PER_BLK + tid;
            const int keep = __ldcg(&g_keep[rowg]);
            s_src[tid] = (b * LL + keep) * D4;
        }
        __syncthreads();

        // 6 independent float4 per thread, loads front-batched for MLP.
        const int out_base = (b * LEN_KEEP + sub * ROWS_PER_BLK) * D4;
        float4 v[6];
        #pragma unroll
        for (int k = 0; k < 6; k++) {
            const int idx = k * THREADS + tid;     // 0..1535
            const int r   = idx / D4;
            const int col = idx - r * D4;
            v[k] = __ldcg(&x[s_src[r] + col]);     // keep x L2-resident
        }
        #pragma unroll
        for (int k = 0; k < 6; k++)
            __stcs(&out4[out_base + k * THREADS + tid], v[k]);

        // Last CTA of this batch resets the handshake for the next replay.
        if (tid == 0) {
            __threadfence();
            const int prev = atomicAdd(&g_done[b], 1);
            if (prev == GATHER_PER_B - 1) {
                g_done[b] = 0;
                g_flag[b] = 0;
            }
        }
    }
}

// ---------------------------------------------------------------------------
extern "C" void kernel_launch(void* const* d_in, const int* in_sizes, int n_in,
                              void* d_out, int out_size)
{
    const float* x       = (const float*)d_in[0];  // (64, 550, 768) f32
    const float* noise   = (const float*)d_in[1];  // (64, 550) f32
    const int*   indexes = (const int*)  d_in[2];  // (64, 3) i32
    float* out = (float*)d_out;  // [x_masked | mask | ids_restore] as f32

    fused_kernel<<<RANK_CTAS + GATHER_CTAS, THREADS>>>(
        (const float4*)x, noise, indexes, out, (float4*)out);
}

// round 8
// speedup vs baseline: 1.1758x; 1.0509x over previous
#include <cuda_runtime.h>
#include <cuda_bf16.h>

// Problem constants
#define BB 64
#define LL 550
#define DD 768
#define RR 3
#define PP 50
#define LEN_KEEP (LL - RR * PP)   // 400
#define D4 (DD / 4)               // 192 float4 per feature row

#define THREADS 256

// Rank: 3 CTAs per batch, one position per thread.
#define RANK_CTAS_PER_B 3
#define RANK_CTAS (BB * RANK_CTAS_PER_B)          // 192
#define SLICE 184                                 // ceil(550/3)

// Gather: exact R3 configuration (proven 22.5us @ 58.9% DRAM).
#define ROWS_PER_BLK 4
#define F4_PER_BLK (ROWS_PER_BLK * D4)            // 768 = 3 * 256
#define GATHER_PER_B (LEN_KEEP / ROWS_PER_BLK)    // 100
#define GATHER_CTAS (BB * GATHER_PER_B)           // 6400

// Scratch + handshake (self-resetting -> graph-replay safe, deterministic).
__device__ int g_keep[BB * LEN_KEEP];
__device__ volatile int g_flag[BB];
__device__ int g_done[BB];

__global__ __launch_bounds__(THREADS)
void fused_kernel(const float4* __restrict__ x,
                  const float*  __restrict__ noise,
                  const int*    __restrict__ indexes,
                  float*        __restrict__ out,
                  float4*       __restrict__ out4)
{
    const int tid = threadIdx.x;
    const int bid = blockIdx.x;

    if (bid < RANK_CTAS) {
        // ---------------- producer: stable rank by counting ----------------
        __shared__ unsigned int sh_bits[LL];

        const int b  = bid / RANK_CTAS_PER_B;
        const int sl = bid - b * RANK_CTAS_PER_B;

        const int i0 = indexes[b * RR + 0];
        const int i1 = indexes[b * RR + 1];
        const int i2 = indexes[b * RR + 2];

        for (int j = tid; j < LL; j += THREADS) {
            const int blk = j / PP;
            float v = (blk == i0 || blk == i1 || blk == i2) ? 2.0f
                                                            : noise[b * LL + j];
            sh_bits[j] = __float_as_uint(v);  // non-negative -> bits ~ value
        }
        __syncthreads();

        const int p = sl * SLICE + tid;            // this thread's position
        if (tid < SLICE && p < LL) {
            const unsigned mybits = sh_bits[p];
            int rank = 0;
            #pragma unroll 10
            for (int j = 0; j < LL; j++) {
                const unsigned bj = sh_bits[j];    // warp-uniform broadcast
                rank += (int)((bj < mybits) || ((bj == mybits) && (j < p)));
            }

            const int OFF_MASK = BB * LEN_KEEP * DD;
            const int OFF_IDS  = OFF_MASK + BB * LL;

            out[OFF_MASK + b * LL + p] = (rank >= LEN_KEEP) ? 1.0f : 0.0f;
            out[OFF_IDS  + b * LL + p] = (float)rank;
            if (rank < LEN_KEEP)
                g_keep[b * LEN_KEEP + rank] = p;   // ids_shuffle[rank] = p
        }

        __syncthreads();
        __threadfence();
        if (tid == 0) atomicAdd((int*)&g_flag[b], 1);
    } else {
        // ---------------- consumer: gather 4 kept rows (R3 shape) ----------
        __shared__ int s_src[ROWS_PER_BLK];

        const int g   = bid - RANK_CTAS;           // 0..6399
        const int b   = g / GATHER_PER_B;
        const int sub = g - b * GATHER_PER_B;      // 0..99

        if (tid == 0) {
            while (g_flag[b] < RANK_CTAS_PER_B) __nanosleep(128);
            __threadfence();                       // acquire
        }
        __syncthreads();

        if (tid < ROWS_PER_BLK) {
            const int rowg = b * LEN_KEEP + sub * ROWS_PER_BLK + tid;
            s_src[tid] = (b * LL + g_keep[rowg]) * D4;
        }
        __syncthreads();

        // 3 independent float4 per thread, streaming cache policy (R3-exact).
        const int out_base = (b * LEN_KEEP + sub * ROWS_PER_BLK) * D4;
        float4 v[3];
        #pragma unroll
        for (int k = 0; k < 3; k++) {
            const int idx = k * THREADS + tid;     // 0..767
            const int r   = idx / D4;
            const int col = idx - r * D4;
            v[k] = __ldcs(&x[s_src[r] + col]);
        }
        #pragma unroll
        for (int k = 0; k < 3; k++)
            __stcs(&out4[out_base + k * THREADS + tid], v[k]);

        // Last gather CTA of this batch resets the handshake for next replay.
        if (tid == 0) {
            const int prev = atomicAdd(&g_done[b], 1);
            if (prev == GATHER_PER_B - 1) {
                g_done[b] = 0;
                g_flag[b] = 0;
            }
        }
    }
}

// ---------------------------------------------------------------------------
extern "C" void kernel_launch(void* const* d_in, const int* in_sizes, int n_in,
                              void* d_out, int out_size)
{
    const float* x       = (const float*)d_in[0];  // (64, 550, 768) f32
    const float* noise   = (const float*)d_in[1];  // (64, 550) f32
    const int*   indexes = (const int*)  d_in[2];  // (64, 3) i32
    float* out = (float*)d_out;  // [x_masked | mask | ids_restore] as f32

    fused_kernel<<<RANK_CTAS + GATHER_CTAS, THREADS>>>(
        (const float4*)x, noise, indexes, out, (float4*)out);
}

// round 12
// speedup vs baseline: 1.2880x; 1.0954x over previous
#include <cuda_runtime.h>
#include <cuda_bf16.h>

// Problem constants
#define BB 64
#define LL 550
#define DD 768
#define RR 3
#define PP 50
#define LEN_KEEP (LL - RR * PP)   // 400
#define D4 (DD / 4)               // 192 float4 per feature row

#define THREADS 256
#define GRID 1184                 // 148 SMs * 8 CTAs -> one resident wave

// Rank duty: 576 low-bid CTAs, 9 per batch, 62 positions each,
// j-loop split across the 8 warps (69-element chunks).
#define RANKERS 576
#define R_PER_B 9                 // rank CTAs per batch (576/64)
#define SLICE_POS 62              // positions per rank CTA (9*62=558>=550)
#define JCHUNK 69                 // j per warp (8*69=552>=550)

// Gather tiles: proven R3 shape. 4 rows x 192 float4, 3 f4/thread.
#define ROWS_PER_TILE 4
#define TILES_PER_B (LEN_KEEP / ROWS_PER_TILE)    // 100
#define NTILES (BB * TILES_PER_B)                 // 6400

// Scratch + handshake (self-resetting -> graph-replay safe).
__device__ int g_keep[BB * LEN_KEEP];
__device__ volatile int g_flag[BB];   // counts rank CTAs done per batch (-> 9)
__device__ int g_fin;                 // CTA completion counter (-> GRID)

__global__ __launch_bounds__(THREADS, 8)
void fused_kernel(const float4* __restrict__ x,
                  const float*  __restrict__ noise,
                  const int*    __restrict__ indexes,
                  float*        __restrict__ out,
                  float4*       __restrict__ out4)
{
    __shared__ unsigned int sh_bits[LL];
    __shared__ int s_part[8 * 64];        // per-warp partial counts
    __shared__ int s_src[ROWS_PER_TILE];

    const int tid  = threadIdx.x;
    const int bid  = blockIdx.x;
    const int warp = tid >> 5;
    const int lane = tid & 31;

    // ======================= phase 1: rank duty =========================
    if (bid < RANKERS) {
        const int b     = bid / R_PER_B;
        const int slice = bid - b * R_PER_B;

        const int i0 = indexes[b * RR + 0];
        const int i1 = indexes[b * RR + 1];
        const int i2 = indexes[b * RR + 2];

        for (int j = tid; j < LL; j += THREADS) {
            const int blk = j / PP;
            float v = (blk == i0 || blk == i1 || blk == i2) ? 2.0f
                                                            : noise[b * LL + j];
            sh_bits[j] = __float_as_uint(v);  // non-negative -> bits ~ value
        }
        __syncthreads();

        // This CTA ranks positions [base, base+n_pos). Lane handles 2.
        const int base  = slice * SLICE_POS;
        const int n_pos = min(SLICE_POS, LL - base);
        const int p0 = base + lane;
        const int p1 = base + 32 + lane;
        const bool v0 = (lane < n_pos);
        const bool v1 = (32 + lane < n_pos);
        const unsigned k0 = v0 ? sh_bits[p0] : 0u;
        const unsigned k1 = v1 ? sh_bits[p1] : 0u;

        // Warp w counts its j-chunk for both positions.
        const int j0 = warp * JCHUNK;
        const int j1 = min(LL, j0 + JCHUNK);
        int c0 = 0, c1 = 0;
        #pragma unroll 4
        for (int j = j0; j < j1; j++) {
            const unsigned bj = sh_bits[j];   // warp-uniform broadcast
            c0 += (int)((bj < k0) || ((bj == k0) && (j < p0)));
            c1 += (int)((bj < k1) || ((bj == k1) && (j < p1)));
        }
        s_part[warp * 64 + lane]      = c0;
        s_part[warp * 64 + 32 + lane] = c1;
        __syncthreads();

        // Reduce 8 partials per position; write outputs.
        if (tid < n_pos) {
            const int p = base + tid;
            int rank = 0;
            #pragma unroll
            for (int w = 0; w < 8; w++) rank += s_part[w * 64 + tid];

            const int OFF_MASK = BB * LEN_KEEP * DD;
            const int OFF_IDS  = OFF_MASK + BB * LL;
            out[OFF_MASK + b * LL + p] = (rank >= LEN_KEEP) ? 1.0f : 0.0f;
            out[OFF_IDS  + b * LL + p] = (float)rank;
            if (rank < LEN_KEEP)
                g_keep[b * LEN_KEEP + rank] = p;   // ids_shuffle[rank] = p
        }

        __syncthreads();
        __threadfence();
        if (tid == 0) atomicAdd((int*)&g_flag[b], 1);
    }

    // ======================= phase 2: persistent gather =================
    for (int t = bid; t < NTILES; t += GRID) {
        const int b   = t / TILES_PER_B;
        const int sub = t - b * TILES_PER_B;

        if (tid == 0) {
            while (g_flag[b] < R_PER_B) __nanosleep(64);
            __threadfence();                      // acquire
        }
        __syncthreads();                          // also guards s_src reuse

        if (tid < ROWS_PER_TILE) {
            const int rowg = b * LEN_KEEP + sub * ROWS_PER_TILE + tid;
            s_src[tid] = (b * LL + g_keep[rowg]) * D4;
        }
        __syncthreads();

        const int out_base = (b * LEN_KEEP + sub * ROWS_PER_TILE) * D4;
        float4 v[3];
        #pragma unroll
        for (int k = 0; k < 3; k++) {
            const int idx = k * THREADS + tid;    // 0..767
            const int r   = idx / D4;
            const int col = idx - r * D4;
            v[k] = __ldcs(&x[s_src[r] + col]);
        }
        #pragma unroll
        for (int k = 0; k < 3; k++)
            __stcs(&out4[out_base + k * THREADS + tid], v[k]);
    }

    // ======================= replay-safe reset ==========================
    __syncthreads();
    if (tid == 0) {
        const int prev = atomicAdd(&g_fin, 1);
        if (prev == GRID - 1) {                   // everyone else is done
            #pragma unroll
            for (int i = 0; i < BB; i++) g_flag[i] = 0;
            g_fin = 0;
        }
    }
}

// ---------------------------------------------------------------------------
extern "C" void kernel_launch(void* const* d_in, const int* in_sizes, int n_in,
                              void* d_out, int out_size)
{
    const float* x       = (const float*)d_in[0];  // (64, 550, 768) f32
    const float* noise   = (const float*)d_in[1];  // (64, 550) f32
    const int*   indexes = (const int*)  d_in[2];  // (64, 3) i32
    float* out = (float*)d_out;  // [x_masked | mask | ids_restore] as f32

    fused_kernel<<<GRID, THREADS>>>(
        (const float4*)x, noise, indexes, out, (float4*)out);
}